// round 14
// baseline (speedup 1.0000x reference)
#include <cuda_runtime.h>
#include <cuda_fp16.h>
#include <math.h>
#include <stdint.h>

#define D_MODEL 1024
#define NHEAD   16
#define DK      64
#define DFF     4096
#define BATCH   2
#define SEQ     2048
#define MTOT    (BATCH*SEQ)   /* 4096 */
#define EPS_RMS 1e-5f
#define QKV_LD  (3*D_MODEL)   /* 3072 */

// ================= low-level helpers (baseline PTX ISA) =================
__device__ __forceinline__ uint32_t smem_to_u32(const void* p) {
    uint32_t a;
    asm("{ .reg .u64 t; cvta.to.shared.u64 t, %1; cvt.u32.u64 %0, t; }" : "=r"(a) : "l"(p));
    return a;
}
__device__ __forceinline__ void cp_async16(uint32_t dst, const void* src) {
    asm volatile("cp.async.cg.shared.global [%0], [%1], 16;" :: "r"(dst), "l"(src));
}
#define CP_COMMIT() asm volatile("cp.async.commit_group;" ::: "memory")
#define CP_WAIT(n)  asm volatile("cp.async.wait_group %0;" :: "n"(n) : "memory")

__device__ __forceinline__ void ldsm_x4(uint32_t& r0, uint32_t& r1, uint32_t& r2, uint32_t& r3,
                                        uint32_t addr) {
    asm volatile("ldmatrix.sync.aligned.m8n8.x4.shared.b16 {%0,%1,%2,%3}, [%4];"
        : "=r"(r0), "=r"(r1), "=r"(r2), "=r"(r3) : "r"(addr));
}
__device__ __forceinline__ void ldsm_x4_t(uint32_t& r0, uint32_t& r1, uint32_t& r2, uint32_t& r3,
                                          uint32_t addr) {
    asm volatile("ldmatrix.sync.aligned.m8n8.x4.trans.shared.b16 {%0,%1,%2,%3}, [%4];"
        : "=r"(r0), "=r"(r1), "=r"(r2), "=r"(r3) : "r"(addr));
}
__device__ __forceinline__ void mma16816(float* c, const uint32_t* a, uint32_t b0, uint32_t b1) {
    asm volatile("mma.sync.aligned.m16n8k16.row.col.f32.f16.f16.f32 "
        "{%0,%1,%2,%3}, {%4,%5,%6,%7}, {%8,%9}, {%0,%1,%2,%3};"
        : "+f"(c[0]), "+f"(c[1]), "+f"(c[2]), "+f"(c[3])
        : "r"(a[0]), "r"(a[1]), "r"(a[2]), "r"(a[3]), "r"(b0), "r"(b1));
}
// fp16-accumulator variant: D/C are 2x b32 (4 halves). Testing legacy-HMMA 2x rate.
__device__ __forceinline__ void mma16816h(uint32_t* c, const uint32_t* a, uint32_t b0, uint32_t b1) {
    asm volatile("mma.sync.aligned.m16n8k16.row.col.f16.f16.f16.f16 "
        "{%0,%1}, {%2,%3,%4,%5}, {%6,%7}, {%0,%1};"
        : "+r"(c[0]), "+r"(c[1])
        : "r"(a[0]), "r"(a[1]), "r"(a[2]), "r"(a[3]), "r"(b0), "r"(b1));
}
__device__ __forceinline__ uint32_t packh2(float a, float b) {
    __half2 h = __floats2half2_rn(a, b);
    return *(uint32_t*)&h;
}

// ================= scratch buffers =================
__device__ __half g_xnh [MTOT*D_MODEL];
__device__ __half g_qkvh[MTOT*QKV_LD];
__device__ __half g_atth[MTOT*D_MODEL];
__device__ float  g_x1  [MTOT*D_MODEL];
__device__ __half g_ffhh[MTOT*DFF];
__device__ __half g_w3h [3*D_MODEL*D_MODEL];   /* concat(wq, wk, wv) */
__device__ __half g_woh [D_MODEL*D_MODEL];
__device__ __half g_w1h [DFF*D_MODEL];
__device__ __half g_w2h [D_MODEL*DFF];

// ================= device bodies =================
__device__ __forceinline__ void rmsnorm_row(
    const float* __restrict__ x, const float* __restrict__ g, __half* __restrict__ y, int row)
{
    const float4* x4 = (const float4*)(x + (size_t)row * D_MODEL);
    const float4* g4 = (const float4*)g;

    float4 v = x4[threadIdx.x];
    float s = v.x*v.x + v.y*v.y + v.z*v.z + v.w*v.w;

    #pragma unroll
    for (int m = 16; m; m >>= 1) s += __shfl_xor_sync(0xffffffffu, s, m);

    __shared__ float red[8];
    int warp = threadIdx.x >> 5, lane = threadIdx.x & 31;
    if (lane == 0) red[warp] = s;
    __syncthreads();
    if (warp == 0) {
        float t = (lane < 8) ? red[lane] : 0.f;
        t += __shfl_xor_sync(0xffffffffu, t, 4);
        t += __shfl_xor_sync(0xffffffffu, t, 2);
        t += __shfl_xor_sync(0xffffffffu, t, 1);
        if (lane == 0) red[0] = t;
    }
    __syncthreads();

    float rms = rsqrtf(red[0] * (1.0f / D_MODEL) + EPS_RMS);
    float4 gg = g4[threadIdx.x];
    __half2* yo = (__half2*)(y + (size_t)row * D_MODEL + threadIdx.x * 4);
    yo[0] = __floats2half2_rn(v.x * rms * gg.x, v.y * rms * gg.y);
    yo[1] = __floats2half2_rn(v.z * rms * gg.z, v.w * rms * gg.w);
}

// ======= fused head: rmsnorm1 (blocks [0,MTOT)) + all weight f2h (rest) =======
__global__ void __launch_bounds__(256) pre_kernel(
    const float* __restrict__ x, const float* __restrict__ g1, __half* __restrict__ xnh,
    const float* __restrict__ wq, const float* __restrict__ wk,
    const float* __restrict__ wv, const float* __restrict__ wo,
    const float* __restrict__ w1, const float* __restrict__ w2,
    __half* __restrict__ w3h, __half* __restrict__ woh,
    __half* __restrict__ w1h, __half* __restrict__ w2h)
{
    if (blockIdx.x < MTOT) {
        rmsnorm_row(x, g1, xnh, blockIdx.x);
        return;
    }
    const long NW = (long)D_MODEL * D_MODEL;
    long i = ((long)(blockIdx.x - MTOT) * 256 + threadIdx.x) * 4;
    const float* src; __half* dst; long off;
    if (i < NW)            { src = wq; dst = w3h;           off = i; }
    else if (i < 2*NW)     { src = wk; dst = w3h + NW;      off = i - NW; }
    else if (i < 3*NW)     { src = wv; dst = w3h + 2*NW;    off = i - 2*NW; }
    else if (i < 4*NW)     { src = wo; dst = woh;           off = i - 3*NW; }
    else if (i < 8*NW)     { src = w1; dst = w1h;           off = i - 4*NW; }
    else                   { src = w2; dst = w2h;           off = i - 8*NW; }
    float4 v = *(const float4*)(src + off);
    ((__half2*)(dst + off))[0] = __floats2half2_rn(v.x, v.y);
    ((__half2*)(dst + off))[1] = __floats2half2_rn(v.z, v.w);
}

__global__ void __launch_bounds__(256) rmsnorm_h_kernel(
    const float* __restrict__ x, const float* __restrict__ g, __half* __restrict__ y)
{
    rmsnorm_row(x, g, y, blockIdx.x);
}

// ================= GELU =================
__device__ __forceinline__ float gelu_f(float v) {
    return 0.5f * v * (1.0f + erff(v * 0.70710678118654752f));
}

// ====== HGEMM v6: R13 shape (128x64 CTA, 8 warps 32x32) + fp16 chunk accum ======
// Tests whether legacy HMMA with fp16 accumulators runs at 2x the fp32-acc rate.
// fp16 accumulation is confined to one K-chunk (64), promoted to fp32 each chunk.
#define KCH    64
#define SPAD   72                          /* 64 + 8 halves padding */
#define HG_ST_A (128 * SPAD * 2)           /* 18432 B per A stage */
#define HG_ST_B (64 * SPAD * 2)            /*  9216 B per B stage */
#define HG_SMEM (2 * HG_ST_A + 2 * HG_ST_B)/* 55296 B */

__device__ __forceinline__ void hg_load_a(
    const __half* __restrict__ G, int base_row, int K, int k0, int tid, uint32_t s_stage)
{
    #pragma unroll
    for (int i = 0; i < 4; i++) {
        int idx = tid + i * 256;
        int row = idx >> 3, seg = idx & 7;
        const __half* src = G + (size_t)(base_row + row) * K + k0 + seg * 8;
        cp_async16(s_stage + (uint32_t)(row * SPAD + seg * 8) * 2, src);
    }
}
__device__ __forceinline__ void hg_load_b(
    const __half* __restrict__ G, int base_row, int K, int k0, int tid, uint32_t s_stage)
{
    #pragma unroll
    for (int i = 0; i < 2; i++) {
        int idx = tid + i * 256;
        int row = idx >> 3, seg = idx & 7;
        const __half* src = G + (size_t)(base_row + row) * K + k0 + seg * 8;
        cp_async16(s_stage + (uint32_t)(row * SPAD + seg * 8) * 2, src);
    }
}

template <int EPI>
__global__ void __launch_bounds__(256, 2) hgemm_mma(
    const __half* __restrict__ A, const __half* __restrict__ B,
    const float* __restrict__ R, float* __restrict__ Cf, __half* __restrict__ Ch,
    int M, int N, int K)
{
    extern __shared__ __half hsm[];
    const uint32_t a_base = smem_to_u32(hsm);
    const uint32_t b_base = a_base + 2 * HG_ST_A;

    const int tid = threadIdx.x;
    const int lane = tid & 31;
    const int wid = tid >> 5;      // 0..7
    const int wy = wid & 3;        // M offset 32*wy
    const int wx = wid >> 2;       // N offset 32*wx
    const int bm = blockIdx.y * 128;
    const int bn = blockIdx.x * 64;

    const int lrow = lane & 15;
    const int koff = (lane >> 4) * 8;

    float acc[2][4][4];            // fp32 master accumulator
    #pragma unroll
    for (int i = 0; i < 2; i++)
        #pragma unroll
        for (int j = 0; j < 4; j++)
            #pragma unroll
            for (int r = 0; r < 4; r++) acc[i][j][r] = 0.f;

    const int nch = K / KCH;

    hg_load_a(A, bm, K, 0, tid, a_base);
    hg_load_b(B, bn, K, 0, tid, b_base);
    CP_COMMIT();
    hg_load_a(A, bm, K, KCH, tid, a_base + HG_ST_A);
    hg_load_b(B, bn, K, KCH, tid, b_base + HG_ST_B);
    CP_COMMIT();

    for (int c = 0; c < nch; ++c) {
        if (c + 1 < nch) { CP_WAIT(1); } else { CP_WAIT(0); }
        __syncthreads();

        const uint32_t a_st = a_base + (uint32_t)(c & 1) * HG_ST_A;
        const uint32_t b_st = b_base + (uint32_t)(c & 1) * HG_ST_B;

        // fp16 chunk accumulators (zeroed each chunk)
        uint32_t hacc[2][4][2];
        #pragma unroll
        for (int i = 0; i < 2; i++)
            #pragma unroll
            for (int j = 0; j < 4; j++) { hacc[i][j][0] = 0u; hacc[i][j][1] = 0u; }

        #pragma unroll
        for (int ks = 0; ks < 4; ++ks) {
            uint32_t af[2][4];
            #pragma unroll
            for (int ma = 0; ma < 2; ++ma) {
                uint32_t addr = a_st +
                    (uint32_t)((wy * 32 + ma * 16 + lrow) * SPAD + ks * 16 + koff) * 2;
                ldsm_x4(af[ma][0], af[ma][1], af[ma][2], af[ma][3], addr);
            }
            uint32_t bf[2][4];
            #pragma unroll
            for (int nb = 0; nb < 2; ++nb) {
                uint32_t addr = b_st +
                    (uint32_t)((wx * 32 + nb * 16 + lrow) * SPAD + ks * 16 + koff) * 2;
                ldsm_x4(bf[nb][0], bf[nb][1], bf[nb][2], bf[nb][3], addr);
            }
            #pragma unroll
            for (int ma = 0; ma < 2; ++ma) {
                #pragma unroll
                for (int na = 0; na < 4; ++na) {
                    const uint32_t b0 = bf[na >> 1][(na & 1)];
                    const uint32_t b1 = bf[na >> 1][(na & 1) + 2];
                    mma16816h(hacc[ma][na], af[ma], b0, b1);
                }
            }
        }

        // promote fp16 chunk sums into fp32 master
        #pragma unroll
        for (int ma = 0; ma < 2; ++ma)
            #pragma unroll
            for (int na = 0; na < 4; ++na) {
                float2 lo = __half22float2(*(__half2*)&hacc[ma][na][0]);
                float2 hi = __half22float2(*(__half2*)&hacc[ma][na][1]);
                acc[ma][na][0] += lo.x; acc[ma][na][1] += lo.y;
                acc[ma][na][2] += hi.x; acc[ma][na][3] += hi.y;
            }

        __syncthreads();

        if (c + 2 < nch) {
            hg_load_a(A, bm, K, (c + 2) * KCH, tid, a_base + (uint32_t)(c & 1) * HG_ST_A);
            hg_load_b(B, bn, K, (c + 2) * KCH, tid, b_base + (uint32_t)(c & 1) * HG_ST_B);
            CP_COMMIT();
        }
    }

    // ---------------- epilogue ----------------
    const int r0 = bm + wy * 32 + (lane >> 2);
    const int c0 = bn + wx * 32 + (lane & 3) * 2;

    #pragma unroll
    for (int ma = 0; ma < 2; ++ma) {
        #pragma unroll
        for (int na = 0; na < 4; ++na) {
            const int row = r0 + ma * 16;
            const int col = c0 + na * 8;
            float* a4 = acc[ma][na];
            if (EPI == 2) {
                *(__half2*)(Ch + (size_t)row * N + col) =
                    __floats2half2_rn(gelu_f(a4[0]), gelu_f(a4[1]));
                *(__half2*)(Ch + (size_t)(row + 8) * N + col) =
                    __floats2half2_rn(gelu_f(a4[2]), gelu_f(a4[3]));
            } else if (EPI == 3) {
                *(__half2*)(Ch + (size_t)row * N + col) = __floats2half2_rn(a4[0], a4[1]);
                *(__half2*)(Ch + (size_t)(row + 8) * N + col) = __floats2half2_rn(a4[2], a4[3]);
            } else {
                float v0 = a4[0], v1 = a4[1], v2 = a4[2], v3 = a4[3];
                float2 ra = *(const float2*)(R + (size_t)row * N + col);
                float2 rb = *(const float2*)(R + (size_t)(row + 8) * N + col);
                v0 += ra.x; v1 += ra.y; v2 += rb.x; v3 += rb.y;
                *(float2*)(Cf + (size_t)row * N + col) = make_float2(v0, v1);
                *(float2*)(Cf + (size_t)(row + 8) * N + col) = make_float2(v2, v3);
            }
        }
    }
}

// ========== flash attention (Round-11 proven version: BQ=64, BKV=64) ==========
#define FP2 72   /* padded row: 64 + 8 halves */

__global__ void __launch_bounds__(128) flash_mma(
    const __half* __restrict__ QKV, __half* __restrict__ O)
{
    __shared__ __half Qs[64][FP2];
    __shared__ __half Ks[2][64][FP2];
    __shared__ __half Vs[2][64][FP2];

    const int tid = threadIdx.x;
    const int lane = tid & 31;
    const int wid = tid >> 5;
    const int qi = (int)(gridDim.x - 1 - blockIdx.x);   // longest first
    const int bh = blockIdx.y;
    const int b = bh >> 4, h = bh & 15;
    const size_t qrow0 = (size_t)(b * SEQ + qi * 64);
    const __half* Qg = QKV + qrow0 * QKV_LD + h * DK;
    const __half* Kg = QKV + (size_t)(b * SEQ) * QKV_LD + D_MODEL + h * DK;
    const __half* Vg = QKV + (size_t)(b * SEQ) * QKV_LD + 2 * D_MODEL + h * DK;

    const uint32_t qs_b = smem_to_u32(&Qs[0][0]);
    const uint32_t ks_b = smem_to_u32(&Ks[0][0][0]);
    const uint32_t vs_b = smem_to_u32(&Vs[0][0][0]);
    const uint32_t kv_stage = 64 * FP2 * 2;

    #pragma unroll
    for (int i = 0; i < 4; i++) {
        int idx = tid + i * 128;
        int r = idx >> 3, s = idx & 7;
        cp_async16(qs_b + (uint32_t)(r * FP2 + s * 8) * 2, Qg + (size_t)r * QKV_LD + s * 8);
    }
    CP_COMMIT();
    #pragma unroll
    for (int i = 0; i < 4; i++) {
        int idx = tid + i * 128;
        int r = idx >> 3, s = idx & 7;
        size_t go = (size_t)r * QKV_LD + s * 8;
        cp_async16(ks_b + (uint32_t)(r * FP2 + s * 8) * 2, Kg + go);
        cp_async16(vs_b + (uint32_t)(r * FP2 + s * 8) * 2, Vg + go);
    }
    CP_COMMIT();
    CP_WAIT(1);
    __syncthreads();

    uint32_t qf[4][4];
    #pragma unroll
    for (int ks = 0; ks < 4; ks++) {
        uint32_t addr = qs_b +
            (uint32_t)((wid * 16 + (lane & 15)) * FP2 + ks * 16 + (lane >> 4) * 8) * 2;
        ldsm_x4(qf[ks][0], qf[ks][1], qf[ks][2], qf[ks][3], addr);
    }

    float o[8][4];
    #pragma unroll
    for (int j = 0; j < 8; j++)
        #pragma unroll
        for (int r = 0; r < 4; r++) o[j][r] = 0.f;
    float m0 = -1e30f, m1 = -1e30f, l0 = 0.f, l1 = 0.f;
    const float scale = 0.125f;

    for (int kt = 0; kt <= qi; ++kt) {
        const int st = kt & 1;
        __syncthreads();
        if (kt < qi) {
            const uint32_t so = (uint32_t)(st ^ 1) * kv_stage;
            #pragma unroll
            for (int i = 0; i < 4; i++) {
                int idx = tid + i * 128;
                int r = idx >> 3, s = idx & 7;
                size_t go = (size_t)((kt + 1) * 64 + r) * QKV_LD + s * 8;
                cp_async16(ks_b + so + (uint32_t)(r * FP2 + s * 8) * 2, Kg + go);
                cp_async16(vs_b + so + (uint32_t)(r * FP2 + s * 8) * 2, Vg + go);
            }
            CP_COMMIT();
            CP_WAIT(1);
        } else {
            CP_WAIT(0);
        }
        __syncthreads();

        float sf[8][4];
        #pragma unroll
        for (int j = 0; j < 8; j++)
            #pragma unroll
            for (int r = 0; r < 4; r++) sf[j][r] = 0.f;

        const uint32_t ks_st = ks_b + (uint32_t)st * kv_stage;
        #pragma unroll
        for (int ks = 0; ks < 4; ks++) {
            #pragma unroll
            for (int nb = 0; nb < 4; nb++) {
                uint32_t r0, r1, r2, r3;
                uint32_t addr = ks_st +
                    (uint32_t)((nb * 16 + (lane & 15)) * FP2 + ks * 16 + (lane >> 4) * 8) * 2;
                ldsm_x4(r0, r1, r2, r3, addr);
                mma16816(sf[nb * 2 + 0], qf[ks], r0, r2);
                mma16816(sf[nb * 2 + 1], qf[ks], r1, r3);
            }
        }

        if (kt == qi) {
            const int rg0 = wid * 16 + (lane >> 2);
            #pragma unroll
            for (int j = 0; j < 8; j++) {
                const int c0 = j * 8 + (lane & 3) * 2;
                sf[j][0] = (c0     > rg0    ) ? -1e30f : sf[j][0] * scale;
                sf[j][1] = (c0 + 1 > rg0    ) ? -1e30f : sf[j][1] * scale;
                sf[j][2] = (c0     > rg0 + 8) ? -1e30f : sf[j][2] * scale;
                sf[j][3] = (c0 + 1 > rg0 + 8) ? -1e30f : sf[j][3] * scale;
            }
        } else {
            #pragma unroll
            for (int j = 0; j < 8; j++) {
                sf[j][0] *= scale; sf[j][1] *= scale;
                sf[j][2] *= scale; sf[j][3] *= scale;
            }
        }

        float t0 = -1e30f, t1 = -1e30f;
        #pragma unroll
        for (int j = 0; j < 8; j++) {
            t0 = fmaxf(t0, fmaxf(sf[j][0], sf[j][1]));
            t1 = fmaxf(t1, fmaxf(sf[j][2], sf[j][3]));
        }
        t0 = fmaxf(t0, __shfl_xor_sync(0xffffffffu, t0, 1));
        t0 = fmaxf(t0, __shfl_xor_sync(0xffffffffu, t0, 2));
        t1 = fmaxf(t1, __shfl_xor_sync(0xffffffffu, t1, 1));
        t1 = fmaxf(t1, __shfl_xor_sync(0xffffffffu, t1, 2));

        const float mn0 = fmaxf(m0, t0), mn1 = fmaxf(m1, t1);
        const float a0 = __expf(m0 - mn0), a1 = __expf(m1 - mn1);
        float ps0 = 0.f, ps1 = 0.f;
        #pragma unroll
        for (int j = 0; j < 8; j++) {
            sf[j][0] = __expf(sf[j][0] - mn0);
            sf[j][1] = __expf(sf[j][1] - mn0);
            sf[j][2] = __expf(sf[j][2] - mn1);
            sf[j][3] = __expf(sf[j][3] - mn1);
            ps0 += sf[j][0] + sf[j][1];
            ps1 += sf[j][2] + sf[j][3];
        }
        ps0 += __shfl_xor_sync(0xffffffffu, ps0, 1);
        ps0 += __shfl_xor_sync(0xffffffffu, ps0, 2);
        ps1 += __shfl_xor_sync(0xffffffffu, ps1, 1);
        ps1 += __shfl_xor_sync(0xffffffffu, ps1, 2);
        l0 = l0 * a0 + ps0; l1 = l1 * a1 + ps1;
        m0 = mn0; m1 = mn1;
        #pragma unroll
        for (int j = 0; j < 8; j++) {
            o[j][0] *= a0; o[j][1] *= a0;
            o[j][2] *= a1; o[j][3] *= a1;
        }

        uint32_t pf[4][4];
        #pragma unroll
        for (int kk = 0; kk < 4; kk++) {
            pf[kk][0] = packh2(sf[2*kk][0],   sf[2*kk][1]);
            pf[kk][1] = packh2(sf[2*kk][2],   sf[2*kk][3]);
            pf[kk][2] = packh2(sf[2*kk+1][0], sf[2*kk+1][1]);
            pf[kk][3] = packh2(sf[2*kk+1][2], sf[2*kk+1][3]);
        }

        const uint32_t vs_st = vs_b + (uint32_t)st * kv_stage;
        #pragma unroll
        for (int kk = 0; kk < 4; kk++) {
            #pragma unroll
            for (int ns = 0; ns < 4; ns++) {
                uint32_t v0, v1, v2, v3;
                uint32_t addr = vs_st +
                    (uint32_t)((kk * 16 + (lane & 7) + 8 * ((lane >> 3) & 1)) * FP2 +
                               ns * 16 + 8 * (lane >> 4)) * 2;
                ldsm_x4_t(v0, v1, v2, v3, addr);
                mma16816(o[2 * ns + 0], pf[kk], v0, v1);
                mma16816(o[2 * ns + 1], pf[kk], v2, v3);
            }
        }
    }

    const float i0 = 1.f / l0, i1 = 1.f / l1;
    const size_t gr0 = qrow0 + wid * 16 + (lane >> 2);
    #pragma unroll
    for (int j = 0; j < 8; j++) {
        const int col = h * DK + j * 8 + (lane & 3) * 2;
        *(__half2*)(O + gr0 * D_MODEL + col) =
            __floats2half2_rn(o[j][0] * i0, o[j][1] * i0);
        *(__half2*)(O + (gr0 + 8) * D_MODEL + col) =
            __floats2half2_rn(o[j][2] * i1, o[j][3] * i1);
    }
}

// ================= host =================
extern "C" void kernel_launch(void* const* d_in, const int* in_sizes, int n_in,
                              void* d_out, int out_size)
{
    const float* x  = (const float*)d_in[0];
    const float* wq = (const float*)d_in[1];
    const float* wk = (const float*)d_in[2];
    const float* wv = (const float*)d_in[3];
    const float* wo = (const float*)d_in[4];
    const float* w1 = (const float*)d_in[5];
    const float* w2 = (const float*)d_in[6];
    const float* g1 = (const float*)d_in[7];
    const float* g2 = (const float*)d_in[8];
    float* out = (float*)d_out;

    __half *xnh, *qkvh, *atth, *ffhh, *w3h, *woh, *w1h, *w2h;
    float *x1;
    cudaGetSymbolAddress((void**)&xnh,  g_xnh);
    cudaGetSymbolAddress((void**)&qkvh, g_qkvh);
    cudaGetSymbolAddress((void**)&atth, g_atth);
    cudaGetSymbolAddress((void**)&x1,   g_x1);
    cudaGetSymbolAddress((void**)&ffhh, g_ffhh);
    cudaGetSymbolAddress((void**)&w3h,  g_w3h);
    cudaGetSymbolAddress((void**)&woh,  g_woh);
    cudaGetSymbolAddress((void**)&w1h,  g_w1h);
    cudaGetSymbolAddress((void**)&w2h,  g_w2h);

    cudaFuncSetAttribute(hgemm_mma<1>, cudaFuncAttributeMaxDynamicSharedMemorySize, HG_SMEM);
    cudaFuncSetAttribute(hgemm_mma<2>, cudaFuncAttributeMaxDynamicSharedMemorySize, HG_SMEM);
    cudaFuncSetAttribute(hgemm_mma<3>, cudaFuncAttributeMaxDynamicSharedMemorySize, HG_SMEM);

    // 0+1. fused: rmsnorm1 (4096 blocks) + all weight f2h (12288 blocks)
    pre_kernel<<<MTOT + (12 * D_MODEL * D_MODEL) / 1024, 256>>>(
        x, g1, xnh, wq, wk, wv, wo, w1, w2, w3h, woh, w1h, w2h);

    // 2. qkv = xn @ [wq|wk|wv]^T   (fused, fp16 out)
    dim3 gqkv(QKV_LD / 64, MTOT / 128);
    hgemm_mma<3><<<gqkv, 256, HG_SMEM>>>(xnh, w3h, nullptr, nullptr, qkvh, MTOT, QKV_LD, D_MODEL);

    // 3. att = causal_attention(q,k,v)
    flash_mma<<<dim3(SEQ / 64, BATCH * NHEAD), 128>>>(qkvh, atth);

    // 4. x1 = x + att @ wo^T
    dim3 gproj(D_MODEL / 64, MTOT / 128);
    hgemm_mma<1><<<gproj, 256, HG_SMEM>>>(atth, woh, x, x1, nullptr, MTOT, D_MODEL, D_MODEL);

    // 5. xn = rmsnorm(x1, g2)
    rmsnorm_h_kernel<<<MTOT, 256>>>(x1, g2, xnh);

    // 6. ffh = gelu(xn @ w1^T)
    dim3 gff1(DFF / 64, MTOT / 128);
    hgemm_mma<2><<<gff1, 256, HG_SMEM>>>(xnh, w1h, nullptr, nullptr, ffhh, MTOT, DFF, D_MODEL);

    // 7. out = x1 + ffh @ w2^T
    hgemm_mma<1><<<gproj, 256, HG_SMEM>>>(ffhh, w2h, x1, out, nullptr, MTOT, D_MODEL, DFF);
}

// round 15
// speedup vs baseline: 1.1377x; 1.1377x over previous
#include <cuda_runtime.h>
#include <cuda_fp16.h>
#include <math.h>
#include <stdint.h>

#define D_MODEL 1024
#define NHEAD   16
#define DK      64
#define DFF     4096
#define BATCH   2
#define SEQ     2048
#define MTOT    (BATCH*SEQ)   /* 4096 */
#define EPS_RMS 1e-5f
#define QKV_LD  (3*D_MODEL)   /* 3072 */

// ================= low-level helpers (baseline PTX ISA) =================
__device__ __forceinline__ uint32_t smem_to_u32(const void* p) {
    uint32_t a;
    asm("{ .reg .u64 t; cvta.to.shared.u64 t, %1; cvt.u32.u64 %0, t; }" : "=r"(a) : "l"(p));
    return a;
}
__device__ __forceinline__ void cp_async16(uint32_t dst, const void* src) {
    asm volatile("cp.async.cg.shared.global [%0], [%1], 16;" :: "r"(dst), "l"(src));
}
#define CP_COMMIT() asm volatile("cp.async.commit_group;" ::: "memory")
#define CP_WAIT(n)  asm volatile("cp.async.wait_group %0;" :: "n"(n) : "memory")

__device__ __forceinline__ void ldsm_x4(uint32_t& r0, uint32_t& r1, uint32_t& r2, uint32_t& r3,
                                        uint32_t addr) {
    asm volatile("ldmatrix.sync.aligned.m8n8.x4.shared.b16 {%0,%1,%2,%3}, [%4];"
        : "=r"(r0), "=r"(r1), "=r"(r2), "=r"(r3) : "r"(addr));
}
__device__ __forceinline__ void ldsm_x4_t(uint32_t& r0, uint32_t& r1, uint32_t& r2, uint32_t& r3,
                                          uint32_t addr) {
    asm volatile("ldmatrix.sync.aligned.m8n8.x4.trans.shared.b16 {%0,%1,%2,%3}, [%4];"
        : "=r"(r0), "=r"(r1), "=r"(r2), "=r"(r3) : "r"(addr));
}
__device__ __forceinline__ void mma16816(float* c, const uint32_t* a, uint32_t b0, uint32_t b1) {
    asm volatile("mma.sync.aligned.m16n8k16.row.col.f32.f16.f16.f32 "
        "{%0,%1,%2,%3}, {%4,%5,%6,%7}, {%8,%9}, {%0,%1,%2,%3};"
        : "+f"(c[0]), "+f"(c[1]), "+f"(c[2]), "+f"(c[3])
        : "r"(a[0]), "r"(a[1]), "r"(a[2]), "r"(a[3]), "r"(b0), "r"(b1));
}
__device__ __forceinline__ uint32_t packh2(float a, float b) {
    __half2 h = __floats2half2_rn(a, b);
    return *(uint32_t*)&h;
}

// ================= scratch buffers =================
__device__ __half g_xnh [MTOT*D_MODEL];
__device__ __half g_qkvh[MTOT*QKV_LD];
__device__ __half g_atth[MTOT*D_MODEL];
__device__ float  g_x1  [MTOT*D_MODEL];
__device__ __half g_ffhh[MTOT*DFF];
__device__ __half g_w3h [3*D_MODEL*D_MODEL];   /* concat(wq, wk, wv) */
__device__ __half g_woh [D_MODEL*D_MODEL];
__device__ __half g_w1h [DFF*D_MODEL];
__device__ __half g_w2h [D_MODEL*DFF];

// ================= device bodies =================
__device__ __forceinline__ void rmsnorm_row(
    const float* __restrict__ x, const float* __restrict__ g, __half* __restrict__ y, int row)
{
    const float4* x4 = (const float4*)(x + (size_t)row * D_MODEL);
    const float4* g4 = (const float4*)g;

    float4 v = x4[threadIdx.x];
    float s = v.x*v.x + v.y*v.y + v.z*v.z + v.w*v.w;

    #pragma unroll
    for (int m = 16; m; m >>= 1) s += __shfl_xor_sync(0xffffffffu, s, m);

    __shared__ float red[8];
    int warp = threadIdx.x >> 5, lane = threadIdx.x & 31;
    if (lane == 0) red[warp] = s;
    __syncthreads();
    if (warp == 0) {
        float t = (lane < 8) ? red[lane] : 0.f;
        t += __shfl_xor_sync(0xffffffffu, t, 4);
        t += __shfl_xor_sync(0xffffffffu, t, 2);
        t += __shfl_xor_sync(0xffffffffu, t, 1);
        if (lane == 0) red[0] = t;
    }
    __syncthreads();

    float rms = rsqrtf(red[0] * (1.0f / D_MODEL) + EPS_RMS);
    float4 gg = g4[threadIdx.x];
    __half2* yo = (__half2*)(y + (size_t)row * D_MODEL + threadIdx.x * 4);
    yo[0] = __floats2half2_rn(v.x * rms * gg.x, v.y * rms * gg.y);
    yo[1] = __floats2half2_rn(v.z * rms * gg.z, v.w * rms * gg.w);
}

// ======= fused head: rmsnorm1 (blocks [0,MTOT)) + all weight f2h (rest) =======
__global__ void __launch_bounds__(256) pre_kernel(
    const float* __restrict__ x, const float* __restrict__ g1, __half* __restrict__ xnh,
    const float* __restrict__ wq, const float* __restrict__ wk,
    const float* __restrict__ wv, const float* __restrict__ wo,
    const float* __restrict__ w1, const float* __restrict__ w2,
    __half* __restrict__ w3h, __half* __restrict__ woh,
    __half* __restrict__ w1h, __half* __restrict__ w2h)
{
    if (blockIdx.x < MTOT) {
        rmsnorm_row(x, g1, xnh, blockIdx.x);
        return;
    }
    const long NW = (long)D_MODEL * D_MODEL;
    long i = ((long)(blockIdx.x - MTOT) * 256 + threadIdx.x) * 4;
    const float* src; __half* dst; long off;
    if (i < NW)            { src = wq; dst = w3h;           off = i; }
    else if (i < 2*NW)     { src = wk; dst = w3h + NW;      off = i - NW; }
    else if (i < 3*NW)     { src = wv; dst = w3h + 2*NW;    off = i - 2*NW; }
    else if (i < 4*NW)     { src = wo; dst = woh;           off = i - 3*NW; }
    else if (i < 8*NW)     { src = w1; dst = w1h;           off = i - 4*NW; }
    else                   { src = w2; dst = w2h;           off = i - 8*NW; }
    float4 v = *(const float4*)(src + off);
    ((__half2*)(dst + off))[0] = __floats2half2_rn(v.x, v.y);
    ((__half2*)(dst + off))[1] = __floats2half2_rn(v.z, v.w);
}

__global__ void __launch_bounds__(256) rmsnorm_h_kernel(
    const float* __restrict__ x, const float* __restrict__ g, __half* __restrict__ y)
{
    rmsnorm_row(x, g, y, blockIdx.x);
}

// ================= GELU =================
__device__ __forceinline__ float gelu_f(float v) {
    return 0.5f * v * (1.0f + erff(v * 0.70710678118654752f));
}

// ====== HGEMM v7: R11 shape (128x128 CTA, 8 warps 64x32) + 3-stage single-barrier ======
// 3 stages let the stage written at iteration c (chunk c+2) be one whose last
// reader was compute(c-1), which all threads finished before this iteration's
// top barrier -> ONE __syncthreads per chunk instead of two.
#define KCH    64
#define SPAD   72                          /* 64 + 8 halves padding */
#define HG_STAGE_B (128 * SPAD * 2)        /* 18432 B per matrix per stage */
#define HG_SMEM    (6 * HG_STAGE_B)        /* 3 stages x (A,B) = 110592 B */

__device__ __forceinline__ void hg_load(
    const __half* __restrict__ G, int base_row, int K, int k0, int tid, uint32_t s_stage)
{
    #pragma unroll
    for (int i = 0; i < 4; i++) {
        int idx = tid + i * 256;              // 0..1023
        int row = idx >> 3, seg = idx & 7;    // 128 rows x 8 16B-segs
        const __half* src = G + (size_t)(base_row + row) * K + k0 + seg * 8;
        cp_async16(s_stage + (uint32_t)(row * SPAD + seg * 8) * 2, src);
    }
}

template <int EPI>
__global__ void __launch_bounds__(256) hgemm_mma(
    const __half* __restrict__ A, const __half* __restrict__ B,
    const float* __restrict__ R, float* __restrict__ Cf, __half* __restrict__ Ch,
    int M, int N, int K)
{
    extern __shared__ __half hsm[];
    const uint32_t a_base = smem_to_u32(hsm);
    const uint32_t b_base = a_base + 3 * HG_STAGE_B;

    const int tid = threadIdx.x;
    const int lane = tid & 31;
    const int wid = tid >> 5;      // 0..7
    const int wy = wid & 1;        // M offset 64*wy
    const int wx = wid >> 1;       // N offset 32*wx
    const int bm = blockIdx.y * 128;
    const int bn = blockIdx.x * 128;

    const int lrow = lane & 15;
    const int koff = (lane >> 4) * 8;

    float acc[4][4][4];
    #pragma unroll
    for (int i = 0; i < 4; i++)
        #pragma unroll
        for (int j = 0; j < 4; j++)
            #pragma unroll
            for (int r = 0; r < 4; r++) acc[i][j][r] = 0.f;

    const int nch = K / KCH;

    hg_load(A, bm, K, 0, tid, a_base);
    hg_load(B, bn, K, 0, tid, b_base);
    CP_COMMIT();
    hg_load(A, bm, K, KCH, tid, a_base + HG_STAGE_B);
    hg_load(B, bn, K, KCH, tid, b_base + HG_STAGE_B);
    CP_COMMIT();

    int st = 0;
    for (int c = 0; c < nch; ++c) {
        if (c + 1 < nch) { CP_WAIT(1); } else { CP_WAIT(0); }
        __syncthreads();               // single barrier per chunk

        const uint32_t a_st = a_base + (uint32_t)st * HG_STAGE_B;
        const uint32_t b_st = b_base + (uint32_t)st * HG_STAGE_B;

        #pragma unroll
        for (int ks = 0; ks < 4; ++ks) {
            uint32_t af[4][4];
            #pragma unroll
            for (int ma = 0; ma < 4; ++ma) {
                uint32_t addr = a_st +
                    (uint32_t)((wy * 64 + ma * 16 + lrow) * SPAD + ks * 16 + koff) * 2;
                ldsm_x4(af[ma][0], af[ma][1], af[ma][2], af[ma][3], addr);
            }
            uint32_t bf[2][4];
            #pragma unroll
            for (int nb = 0; nb < 2; ++nb) {
                uint32_t addr = b_st +
                    (uint32_t)((wx * 32 + nb * 16 + lrow) * SPAD + ks * 16 + koff) * 2;
                ldsm_x4(bf[nb][0], bf[nb][1], bf[nb][2], bf[nb][3], addr);
            }
            #pragma unroll
            for (int ma = 0; ma < 4; ++ma) {
                #pragma unroll
                for (int na = 0; na < 4; ++na) {
                    const uint32_t b0 = bf[na >> 1][(na & 1)];
                    const uint32_t b1 = bf[na >> 1][(na & 1) + 2];
                    mma16816(acc[ma][na], af[ma], b0, b1);
                }
            }
        }

        if (c + 2 < nch) {
            const int sp = (st + 2 >= 3) ? st - 1 : st + 2;   // (c+2) % 3
            hg_load(A, bm, K, (c + 2) * KCH, tid, a_base + (uint32_t)sp * HG_STAGE_B);
            hg_load(B, bn, K, (c + 2) * KCH, tid, b_base + (uint32_t)sp * HG_STAGE_B);
            CP_COMMIT();
        }
        st = (st + 1 >= 3) ? 0 : st + 1;
    }

    // ---------------- epilogue ----------------
    const int r0 = bm + wy * 64 + (lane >> 2);
    const int c0 = bn + wx * 32 + (lane & 3) * 2;

    #pragma unroll
    for (int ma = 0; ma < 4; ++ma) {
        #pragma unroll
        for (int na = 0; na < 4; ++na) {
            const int row = r0 + ma * 16;
            const int col = c0 + na * 8;
            float* a4 = acc[ma][na];
            if (EPI == 2) {
                *(__half2*)(Ch + (size_t)row * N + col) =
                    __floats2half2_rn(gelu_f(a4[0]), gelu_f(a4[1]));
                *(__half2*)(Ch + (size_t)(row + 8) * N + col) =
                    __floats2half2_rn(gelu_f(a4[2]), gelu_f(a4[3]));
            } else if (EPI == 3) {
                *(__half2*)(Ch + (size_t)row * N + col) = __floats2half2_rn(a4[0], a4[1]);
                *(__half2*)(Ch + (size_t)(row + 8) * N + col) = __floats2half2_rn(a4[2], a4[3]);
            } else {
                float v0 = a4[0], v1 = a4[1], v2 = a4[2], v3 = a4[3];
                float2 ra = *(const float2*)(R + (size_t)row * N + col);
                float2 rb = *(const float2*)(R + (size_t)(row + 8) * N + col);
                v0 += ra.x; v1 += ra.y; v2 += rb.x; v3 += rb.y;
                *(float2*)(Cf + (size_t)row * N + col) = make_float2(v0, v1);
                *(float2*)(Cf + (size_t)(row + 8) * N + col) = make_float2(v2, v3);
            }
        }
    }
}

// ========== flash attention (Round-11 proven version: BQ=64, BKV=64) ==========
#define FP2 72   /* padded row: 64 + 8 halves */

__global__ void __launch_bounds__(128) flash_mma(
    const __half* __restrict__ QKV, __half* __restrict__ O)
{
    __shared__ __half Qs[64][FP2];
    __shared__ __half Ks[2][64][FP2];
    __shared__ __half Vs[2][64][FP2];

    const int tid = threadIdx.x;
    const int lane = tid & 31;
    const int wid = tid >> 5;
    const int qi = (int)(gridDim.x - 1 - blockIdx.x);   // longest first
    const int bh = blockIdx.y;
    const int b = bh >> 4, h = bh & 15;
    const size_t qrow0 = (size_t)(b * SEQ + qi * 64);
    const __half* Qg = QKV + qrow0 * QKV_LD + h * DK;
    const __half* Kg = QKV + (size_t)(b * SEQ) * QKV_LD + D_MODEL + h * DK;
    const __half* Vg = QKV + (size_t)(b * SEQ) * QKV_LD + 2 * D_MODEL + h * DK;

    const uint32_t qs_b = smem_to_u32(&Qs[0][0]);
    const uint32_t ks_b = smem_to_u32(&Ks[0][0][0]);
    const uint32_t vs_b = smem_to_u32(&Vs[0][0][0]);
    const uint32_t kv_stage = 64 * FP2 * 2;

    #pragma unroll
    for (int i = 0; i < 4; i++) {
        int idx = tid + i * 128;
        int r = idx >> 3, s = idx & 7;
        cp_async16(qs_b + (uint32_t)(r * FP2 + s * 8) * 2, Qg + (size_t)r * QKV_LD + s * 8);
    }
    CP_COMMIT();
    #pragma unroll
    for (int i = 0; i < 4; i++) {
        int idx = tid + i * 128;
        int r = idx >> 3, s = idx & 7;
        size_t go = (size_t)r * QKV_LD + s * 8;
        cp_async16(ks_b + (uint32_t)(r * FP2 + s * 8) * 2, Kg + go);
        cp_async16(vs_b + (uint32_t)(r * FP2 + s * 8) * 2, Vg + go);
    }
    CP_COMMIT();
    CP_WAIT(1);
    __syncthreads();

    uint32_t qf[4][4];
    #pragma unroll
    for (int ks = 0; ks < 4; ks++) {
        uint32_t addr = qs_b +
            (uint32_t)((wid * 16 + (lane & 15)) * FP2 + ks * 16 + (lane >> 4) * 8) * 2;
        ldsm_x4(qf[ks][0], qf[ks][1], qf[ks][2], qf[ks][3], addr);
    }

    float o[8][4];
    #pragma unroll
    for (int j = 0; j < 8; j++)
        #pragma unroll
        for (int r = 0; r < 4; r++) o[j][r] = 0.f;
    float m0 = -1e30f, m1 = -1e30f, l0 = 0.f, l1 = 0.f;
    const float scale = 0.125f;

    for (int kt = 0; kt <= qi; ++kt) {
        const int st = kt & 1;
        __syncthreads();
        if (kt < qi) {
            const uint32_t so = (uint32_t)(st ^ 1) * kv_stage;
            #pragma unroll
            for (int i = 0; i < 4; i++) {
                int idx = tid + i * 128;
                int r = idx >> 3, s = idx & 7;
                size_t go = (size_t)((kt + 1) * 64 + r) * QKV_LD + s * 8;
                cp_async16(ks_b + so + (uint32_t)(r * FP2 + s * 8) * 2, Kg + go);
                cp_async16(vs_b + so + (uint32_t)(r * FP2 + s * 8) * 2, Vg + go);
            }
            CP_COMMIT();
            CP_WAIT(1);
        } else {
            CP_WAIT(0);
        }
        __syncthreads();

        float sf[8][4];
        #pragma unroll
        for (int j = 0; j < 8; j++)
            #pragma unroll
            for (int r = 0; r < 4; r++) sf[j][r] = 0.f;

        const uint32_t ks_st = ks_b + (uint32_t)st * kv_stage;
        #pragma unroll
        for (int ks = 0; ks < 4; ks++) {
            #pragma unroll
            for (int nb = 0; nb < 4; nb++) {
                uint32_t r0, r1, r2, r3;
                uint32_t addr = ks_st +
                    (uint32_t)((nb * 16 + (lane & 15)) * FP2 + ks * 16 + (lane >> 4) * 8) * 2;
                ldsm_x4(r0, r1, r2, r3, addr);
                mma16816(sf[nb * 2 + 0], qf[ks], r0, r2);
                mma16816(sf[nb * 2 + 1], qf[ks], r1, r3);
            }
        }

        if (kt == qi) {
            const int rg0 = wid * 16 + (lane >> 2);
            #pragma unroll
            for (int j = 0; j < 8; j++) {
                const int c0 = j * 8 + (lane & 3) * 2;
                sf[j][0] = (c0     > rg0    ) ? -1e30f : sf[j][0] * scale;
                sf[j][1] = (c0 + 1 > rg0    ) ? -1e30f : sf[j][1] * scale;
                sf[j][2] = (c0     > rg0 + 8) ? -1e30f : sf[j][2] * scale;
                sf[j][3] = (c0 + 1 > rg0 + 8) ? -1e30f : sf[j][3] * scale;
            }
        } else {
            #pragma unroll
            for (int j = 0; j < 8; j++) {
                sf[j][0] *= scale; sf[j][1] *= scale;
                sf[j][2] *= scale; sf[j][3] *= scale;
            }
        }

        float t0 = -1e30f, t1 = -1e30f;
        #pragma unroll
        for (int j = 0; j < 8; j++) {
            t0 = fmaxf(t0, fmaxf(sf[j][0], sf[j][1]));
            t1 = fmaxf(t1, fmaxf(sf[j][2], sf[j][3]));
        }
        t0 = fmaxf(t0, __shfl_xor_sync(0xffffffffu, t0, 1));
        t0 = fmaxf(t0, __shfl_xor_sync(0xffffffffu, t0, 2));
        t1 = fmaxf(t1, __shfl_xor_sync(0xffffffffu, t1, 1));
        t1 = fmaxf(t1, __shfl_xor_sync(0xffffffffu, t1, 2));

        const float mn0 = fmaxf(m0, t0), mn1 = fmaxf(m1, t1);
        const float a0 = __expf(m0 - mn0), a1 = __expf(m1 - mn1);
        float ps0 = 0.f, ps1 = 0.f;
        #pragma unroll
        for (int j = 0; j < 8; j++) {
            sf[j][0] = __expf(sf[j][0] - mn0);
            sf[j][1] = __expf(sf[j][1] - mn0);
            sf[j][2] = __expf(sf[j][2] - mn1);
            sf[j][3] = __expf(sf[j][3] - mn1);
            ps0 += sf[j][0] + sf[j][1];
            ps1 += sf[j][2] + sf[j][3];
        }
        ps0 += __shfl_xor_sync(0xffffffffu, ps0, 1);
        ps0 += __shfl_xor_sync(0xffffffffu, ps0, 2);
        ps1 += __shfl_xor_sync(0xffffffffu, ps1, 1);
        ps1 += __shfl_xor_sync(0xffffffffu, ps1, 2);
        l0 = l0 * a0 + ps0; l1 = l1 * a1 + ps1;
        m0 = mn0; m1 = mn1;
        #pragma unroll
        for (int j = 0; j < 8; j++) {
            o[j][0] *= a0; o[j][1] *= a0;
            o[j][2] *= a1; o[j][3] *= a1;
        }

        uint32_t pf[4][4];
        #pragma unroll
        for (int kk = 0; kk < 4; kk++) {
            pf[kk][0] = packh2(sf[2*kk][0],   sf[2*kk][1]);
            pf[kk][1] = packh2(sf[2*kk][2],   sf[2*kk][3]);
            pf[kk][2] = packh2(sf[2*kk+1][0], sf[2*kk+1][1]);
            pf[kk][3] = packh2(sf[2*kk+1][2], sf[2*kk+1][3]);
        }

        const uint32_t vs_st = vs_b + (uint32_t)st * kv_stage;
        #pragma unroll
        for (int kk = 0; kk < 4; kk++) {
            #pragma unroll
            for (int ns = 0; ns < 4; ns++) {
                uint32_t v0, v1, v2, v3;
                uint32_t addr = vs_st +
                    (uint32_t)((kk * 16 + (lane & 7) + 8 * ((lane >> 3) & 1)) * FP2 +
                               ns * 16 + 8 * (lane >> 4)) * 2;
                ldsm_x4_t(v0, v1, v2, v3, addr);
                mma16816(o[2 * ns + 0], pf[kk], v0, v1);
                mma16816(o[2 * ns + 1], pf[kk], v2, v3);
            }
        }
    }

    const float i0 = 1.f / l0, i1 = 1.f / l1;
    const size_t gr0 = qrow0 + wid * 16 + (lane >> 2);
    #pragma unroll
    for (int j = 0; j < 8; j++) {
        const int col = h * DK + j * 8 + (lane & 3) * 2;
        *(__half2*)(O + gr0 * D_MODEL + col) =
            __floats2half2_rn(o[j][0] * i0, o[j][1] * i0);
        *(__half2*)(O + (gr0 + 8) * D_MODEL + col) =
            __floats2half2_rn(o[j][2] * i1, o[j][3] * i1);
    }
}

// ================= host =================
extern "C" void kernel_launch(void* const* d_in, const int* in_sizes, int n_in,
                              void* d_out, int out_size)
{
    const float* x  = (const float*)d_in[0];
    const float* wq = (const float*)d_in[1];
    const float* wk = (const float*)d_in[2];
    const float* wv = (const float*)d_in[3];
    const float* wo = (const float*)d_in[4];
    const float* w1 = (const float*)d_in[5];
    const float* w2 = (const float*)d_in[6];
    const float* g1 = (const float*)d_in[7];
    const float* g2 = (const float*)d_in[8];
    float* out = (float*)d_out;

    __half *xnh, *qkvh, *atth, *ffhh, *w3h, *woh, *w1h, *w2h;
    float *x1;
    cudaGetSymbolAddress((void**)&xnh,  g_xnh);
    cudaGetSymbolAddress((void**)&qkvh, g_qkvh);
    cudaGetSymbolAddress((void**)&atth, g_atth);
    cudaGetSymbolAddress((void**)&x1,   g_x1);
    cudaGetSymbolAddress((void**)&ffhh, g_ffhh);
    cudaGetSymbolAddress((void**)&w3h,  g_w3h);
    cudaGetSymbolAddress((void**)&woh,  g_woh);
    cudaGetSymbolAddress((void**)&w1h,  g_w1h);
    cudaGetSymbolAddress((void**)&w2h,  g_w2h);

    cudaFuncSetAttribute(hgemm_mma<1>, cudaFuncAttributeMaxDynamicSharedMemorySize, HG_SMEM);
    cudaFuncSetAttribute(hgemm_mma<2>, cudaFuncAttributeMaxDynamicSharedMemorySize, HG_SMEM);
    cudaFuncSetAttribute(hgemm_mma<3>, cudaFuncAttributeMaxDynamicSharedMemorySize, HG_SMEM);

    // 0+1. fused: rmsnorm1 (4096 blocks) + all weight f2h (12288 blocks)
    pre_kernel<<<MTOT + (12 * D_MODEL * D_MODEL) / 1024, 256>>>(
        x, g1, xnh, wq, wk, wv, wo, w1, w2, w3h, woh, w1h, w2h);

    // 2. qkv = xn @ [wq|wk|wv]^T   (fused, fp16 out)
    dim3 gqkv(QKV_LD / 128, MTOT / 128);
    hgemm_mma<3><<<gqkv, 256, HG_SMEM>>>(xnh, w3h, nullptr, nullptr, qkvh, MTOT, QKV_LD, D_MODEL);

    // 3. att = causal_attention(q,k,v)
    flash_mma<<<dim3(SEQ / 64, BATCH * NHEAD), 128>>>(qkvh, atth);

    // 4. x1 = x + att @ wo^T
    dim3 gproj(D_MODEL / 128, MTOT / 128);
    hgemm_mma<1><<<gproj, 256, HG_SMEM>>>(atth, woh, x, x1, nullptr, MTOT, D_MODEL, D_MODEL);

    // 5. xn = rmsnorm(x1, g2)
    rmsnorm_h_kernel<<<MTOT, 256>>>(x1, g2, xnh);

    // 6. ffh = gelu(xn @ w1^T)
    dim3 gff1(DFF / 128, MTOT / 128);
    hgemm_mma<2><<<gff1, 256, HG_SMEM>>>(xnh, w1h, nullptr, nullptr, ffhh, MTOT, DFF, D_MODEL);

    // 7. out = x1 + ffh @ w2^T
    hgemm_mma<1><<<gproj, 256, HG_SMEM>>>(ffhh, w2h, x1, out, nullptr, MTOT, D_MODEL, DFF);
}

// round 16
// speedup vs baseline: 1.1426x; 1.0042x over previous
#include <cuda_runtime.h>
#include <cuda_fp16.h>
#include <math.h>
#include <stdint.h>

#define D_MODEL 1024
#define NHEAD   16
#define DK      64
#define DFF     4096
#define BATCH   2
#define SEQ     2048
#define MTOT    (BATCH*SEQ)   /* 4096 */
#define EPS_RMS 1e-5f
#define QKV_LD  (3*D_MODEL)   /* 3072 */

// ================= low-level helpers (baseline PTX ISA) =================
__device__ __forceinline__ uint32_t smem_to_u32(const void* p) {
    uint32_t a;
    asm("{ .reg .u64 t; cvta.to.shared.u64 t, %1; cvt.u32.u64 %0, t; }" : "=r"(a) : "l"(p));
    return a;
}
__device__ __forceinline__ void cp_async16(uint32_t dst, const void* src) {
    asm volatile("cp.async.cg.shared.global [%0], [%1], 16;" :: "r"(dst), "l"(src));
}
#define CP_COMMIT() asm volatile("cp.async.commit_group;" ::: "memory")
#define CP_WAIT(n)  asm volatile("cp.async.wait_group %0;" :: "n"(n) : "memory")

__device__ __forceinline__ void ldsm_x4(uint32_t& r0, uint32_t& r1, uint32_t& r2, uint32_t& r3,
                                        uint32_t addr) {
    asm volatile("ldmatrix.sync.aligned.m8n8.x4.shared.b16 {%0,%1,%2,%3}, [%4];"
        : "=r"(r0), "=r"(r1), "=r"(r2), "=r"(r3) : "r"(addr));
}
__device__ __forceinline__ void ldsm_x4_t(uint32_t& r0, uint32_t& r1, uint32_t& r2, uint32_t& r3,
                                          uint32_t addr) {
    asm volatile("ldmatrix.sync.aligned.m8n8.x4.trans.shared.b16 {%0,%1,%2,%3}, [%4];"
        : "=r"(r0), "=r"(r1), "=r"(r2), "=r"(r3) : "r"(addr));
}
__device__ __forceinline__ void mma16816(float* c, const uint32_t* a, uint32_t b0, uint32_t b1) {
    asm volatile("mma.sync.aligned.m16n8k16.row.col.f32.f16.f16.f32 "
        "{%0,%1,%2,%3}, {%4,%5,%6,%7}, {%8,%9}, {%0,%1,%2,%3};"
        : "+f"(c[0]), "+f"(c[1]), "+f"(c[2]), "+f"(c[3])
        : "r"(a[0]), "r"(a[1]), "r"(a[2]), "r"(a[3]), "r"(b0), "r"(b1));
}
__device__ __forceinline__ uint32_t packh2(float a, float b) {
    __half2 h = __floats2half2_rn(a, b);
    return *(uint32_t*)&h;
}

// ================= scratch buffers =================
__device__ __half g_xnh [MTOT*D_MODEL];
__device__ __half g_qkvh[MTOT*QKV_LD];
__device__ __half g_atth[MTOT*D_MODEL];
__device__ float  g_x1  [MTOT*D_MODEL];
__device__ __half g_ffhh[MTOT*DFF];
__device__ __half g_w3h [3*D_MODEL*D_MODEL];   /* concat(wq, wk, wv) */
__device__ __half g_woh [D_MODEL*D_MODEL];
__device__ __half g_w1h [DFF*D_MODEL];
__device__ __half g_w2h [D_MODEL*DFF];

// ================= device bodies =================
__device__ __forceinline__ void rmsnorm_row(
    const float* __restrict__ x, const float* __restrict__ g, __half* __restrict__ y, int row)
{
    const float4* x4 = (const float4*)(x + (size_t)row * D_MODEL);
    const float4* g4 = (const float4*)g;

    float4 v = x4[threadIdx.x];
    float s = v.x*v.x + v.y*v.y + v.z*v.z + v.w*v.w;

    #pragma unroll
    for (int m = 16; m; m >>= 1) s += __shfl_xor_sync(0xffffffffu, s, m);

    __shared__ float red[8];
    int warp = threadIdx.x >> 5, lane = threadIdx.x & 31;
    if (lane == 0) red[warp] = s;
    __syncthreads();
    if (warp == 0) {
        float t = (lane < 8) ? red[lane] : 0.f;
        t += __shfl_xor_sync(0xffffffffu, t, 4);
        t += __shfl_xor_sync(0xffffffffu, t, 2);
        t += __shfl_xor_sync(0xffffffffu, t, 1);
        if (lane == 0) red[0] = t;
    }
    __syncthreads();

    float rms = rsqrtf(red[0] * (1.0f / D_MODEL) + EPS_RMS);
    float4 gg = g4[threadIdx.x];
    __half2* yo = (__half2*)(y + (size_t)row * D_MODEL + threadIdx.x * 4);
    yo[0] = __floats2half2_rn(v.x * rms * gg.x, v.y * rms * gg.y);
    yo[1] = __floats2half2_rn(v.z * rms * gg.z, v.w * rms * gg.w);
}

// ======= fused head: rmsnorm1 (blocks [0,MTOT)) + all weight f2h (rest) =======
__global__ void __launch_bounds__(256) pre_kernel(
    const float* __restrict__ x, const float* __restrict__ g1, __half* __restrict__ xnh,
    const float* __restrict__ wq, const float* __restrict__ wk,
    const float* __restrict__ wv, const float* __restrict__ wo,
    const float* __restrict__ w1, const float* __restrict__ w2,
    __half* __restrict__ w3h, __half* __restrict__ woh,
    __half* __restrict__ w1h, __half* __restrict__ w2h)
{
    if (blockIdx.x < MTOT) {
        rmsnorm_row(x, g1, xnh, blockIdx.x);
        return;
    }
    const long NW = (long)D_MODEL * D_MODEL;
    long i = ((long)(blockIdx.x - MTOT) * 256 + threadIdx.x) * 4;
    const float* src; __half* dst; long off;
    if (i < NW)            { src = wq; dst = w3h;           off = i; }
    else if (i < 2*NW)     { src = wk; dst = w3h + NW;      off = i - NW; }
    else if (i < 3*NW)     { src = wv; dst = w3h + 2*NW;    off = i - 2*NW; }
    else if (i < 4*NW)     { src = wo; dst = woh;           off = i - 3*NW; }
    else if (i < 8*NW)     { src = w1; dst = w1h;           off = i - 4*NW; }
    else                   { src = w2; dst = w2h;           off = i - 8*NW; }
    float4 v = *(const float4*)(src + off);
    ((__half2*)(dst + off))[0] = __floats2half2_rn(v.x, v.y);
    ((__half2*)(dst + off))[1] = __floats2half2_rn(v.z, v.w);
}

__global__ void __launch_bounds__(256) rmsnorm_h_kernel(
    const float* __restrict__ x, const float* __restrict__ g, __half* __restrict__ y)
{
    rmsnorm_row(x, g, y, blockIdx.x);
}

// ================= GELU =================
__device__ __forceinline__ float gelu_f(float v) {
    return 0.5f * v * (1.0f + erff(v * 0.70710678118654752f));
}

// ====== HGEMM v7 (R15 winner): 128x128 CTA, 8 warps 64x32, 3-stage 1-barrier ======
#define KCH    64
#define SPAD   72                          /* 64 + 8 halves padding */
#define HG_STAGE_B (128 * SPAD * 2)        /* 18432 B per matrix per stage */
#define HG_SMEM    (6 * HG_STAGE_B)        /* 3 stages x (A,B) = 110592 B */

__device__ __forceinline__ void hg_load(
    const __half* __restrict__ G, int base_row, int K, int k0, int tid, uint32_t s_stage)
{
    #pragma unroll
    for (int i = 0; i < 4; i++) {
        int idx = tid + i * 256;              // 0..1023
        int row = idx >> 3, seg = idx & 7;    // 128 rows x 8 16B-segs
        const __half* src = G + (size_t)(base_row + row) * K + k0 + seg * 8;
        cp_async16(s_stage + (uint32_t)(row * SPAD + seg * 8) * 2, src);
    }
}

template <int EPI>
__global__ void __launch_bounds__(256) hgemm_mma(
    const __half* __restrict__ A, const __half* __restrict__ B,
    const float* __restrict__ R, float* __restrict__ Cf, __half* __restrict__ Ch,
    int M, int N, int K)
{
    extern __shared__ __half hsm[];
    const uint32_t a_base = smem_to_u32(hsm);
    const uint32_t b_base = a_base + 3 * HG_STAGE_B;

    const int tid = threadIdx.x;
    const int lane = tid & 31;
    const int wid = tid >> 5;      // 0..7
    const int wy = wid & 1;        // M offset 64*wy
    const int wx = wid >> 1;       // N offset 32*wx
    const int bm = blockIdx.y * 128;
    const int bn = blockIdx.x * 128;

    const int lrow = lane & 15;
    const int koff = (lane >> 4) * 8;

    float acc[4][4][4];
    #pragma unroll
    for (int i = 0; i < 4; i++)
        #pragma unroll
        for (int j = 0; j < 4; j++)
            #pragma unroll
            for (int r = 0; r < 4; r++) acc[i][j][r] = 0.f;

    const int nch = K / KCH;

    hg_load(A, bm, K, 0, tid, a_base);
    hg_load(B, bn, K, 0, tid, b_base);
    CP_COMMIT();
    hg_load(A, bm, K, KCH, tid, a_base + HG_STAGE_B);
    hg_load(B, bn, K, KCH, tid, b_base + HG_STAGE_B);
    CP_COMMIT();

    int st = 0;
    for (int c = 0; c < nch; ++c) {
        if (c + 1 < nch) { CP_WAIT(1); } else { CP_WAIT(0); }
        __syncthreads();               // single barrier per chunk

        const uint32_t a_st = a_base + (uint32_t)st * HG_STAGE_B;
        const uint32_t b_st = b_base + (uint32_t)st * HG_STAGE_B;

        #pragma unroll
        for (int ks = 0; ks < 4; ++ks) {
            uint32_t af[4][4];
            #pragma unroll
            for (int ma = 0; ma < 4; ++ma) {
                uint32_t addr = a_st +
                    (uint32_t)((wy * 64 + ma * 16 + lrow) * SPAD + ks * 16 + koff) * 2;
                ldsm_x4(af[ma][0], af[ma][1], af[ma][2], af[ma][3], addr);
            }
            uint32_t bf[2][4];
            #pragma unroll
            for (int nb = 0; nb < 2; ++nb) {
                uint32_t addr = b_st +
                    (uint32_t)((wx * 32 + nb * 16 + lrow) * SPAD + ks * 16 + koff) * 2;
                ldsm_x4(bf[nb][0], bf[nb][1], bf[nb][2], bf[nb][3], addr);
            }
            #pragma unroll
            for (int ma = 0; ma < 4; ++ma) {
                #pragma unroll
                for (int na = 0; na < 4; ++na) {
                    const uint32_t b0 = bf[na >> 1][(na & 1)];
                    const uint32_t b1 = bf[na >> 1][(na & 1) + 2];
                    mma16816(acc[ma][na], af[ma], b0, b1);
                }
            }
        }

        if (c + 2 < nch) {
            const int sp = (st + 2 >= 3) ? st - 1 : st + 2;   // (c+2) % 3
            hg_load(A, bm, K, (c + 2) * KCH, tid, a_base + (uint32_t)sp * HG_STAGE_B);
            hg_load(B, bn, K, (c + 2) * KCH, tid, b_base + (uint32_t)sp * HG_STAGE_B);
            CP_COMMIT();
        }
        st = (st + 1 >= 3) ? 0 : st + 1;
    }

    // ---------------- epilogue ----------------
    const int r0 = bm + wy * 64 + (lane >> 2);
    const int c0 = bn + wx * 32 + (lane & 3) * 2;

    #pragma unroll
    for (int ma = 0; ma < 4; ++ma) {
        #pragma unroll
        for (int na = 0; na < 4; ++na) {
            const int row = r0 + ma * 16;
            const int col = c0 + na * 8;
            float* a4 = acc[ma][na];
            if (EPI == 2) {
                *(__half2*)(Ch + (size_t)row * N + col) =
                    __floats2half2_rn(gelu_f(a4[0]), gelu_f(a4[1]));
                *(__half2*)(Ch + (size_t)(row + 8) * N + col) =
                    __floats2half2_rn(gelu_f(a4[2]), gelu_f(a4[3]));
            } else if (EPI == 3) {
                *(__half2*)(Ch + (size_t)row * N + col) = __floats2half2_rn(a4[0], a4[1]);
                *(__half2*)(Ch + (size_t)(row + 8) * N + col) = __floats2half2_rn(a4[2], a4[3]);
            } else {
                float v0 = a4[0], v1 = a4[1], v2 = a4[2], v3 = a4[3];
                float2 ra = *(const float2*)(R + (size_t)row * N + col);
                float2 rb = *(const float2*)(R + (size_t)(row + 8) * N + col);
                v0 += ra.x; v1 += ra.y; v2 += rb.x; v3 += rb.y;
                *(float2*)(Cf + (size_t)row * N + col) = make_float2(v0, v1);
                *(float2*)(Cf + (size_t)(row + 8) * N + col) = make_float2(v2, v3);
            }
        }
    }
}

// ========== flash attention v4: BQ=64, BKV=64, SINGLE barrier per KV tile ==========
// Reorder: CP_WAIT(0) -> one __syncthreads -> issue next loads -> compute.
// Barrier both publishes this tile's cp.async arrivals and frees stage st^1
// (read by compute(kt-1)). Smem unchanged (46 KB static -> 4 CTAs/SM kept).
#define FP2 72   /* padded row: 64 + 8 halves */

__global__ void __launch_bounds__(128) flash_mma(
    const __half* __restrict__ QKV, __half* __restrict__ O)
{
    __shared__ __half Qs[64][FP2];
    __shared__ __half Ks[2][64][FP2];
    __shared__ __half Vs[2][64][FP2];

    const int tid = threadIdx.x;
    const int lane = tid & 31;
    const int wid = tid >> 5;
    const int qi = (int)(gridDim.x - 1 - blockIdx.x);   // longest first
    const int bh = blockIdx.y;
    const int b = bh >> 4, h = bh & 15;
    const size_t qrow0 = (size_t)(b * SEQ + qi * 64);
    const __half* Qg = QKV + qrow0 * QKV_LD + h * DK;
    const __half* Kg = QKV + (size_t)(b * SEQ) * QKV_LD + D_MODEL + h * DK;
    const __half* Vg = QKV + (size_t)(b * SEQ) * QKV_LD + 2 * D_MODEL + h * DK;

    const uint32_t qs_b = smem_to_u32(&Qs[0][0]);
    const uint32_t ks_b = smem_to_u32(&Ks[0][0][0]);
    const uint32_t vs_b = smem_to_u32(&Vs[0][0][0]);
    const uint32_t kv_stage = 64 * FP2 * 2;

    // prologue: Q + KV0, one group each
    #pragma unroll
    for (int i = 0; i < 4; i++) {
        int idx = tid + i * 128;
        int r = idx >> 3, s = idx & 7;
        cp_async16(qs_b + (uint32_t)(r * FP2 + s * 8) * 2, Qg + (size_t)r * QKV_LD + s * 8);
    }
    CP_COMMIT();
    #pragma unroll
    for (int i = 0; i < 4; i++) {
        int idx = tid + i * 128;
        int r = idx >> 3, s = idx & 7;
        size_t go = (size_t)r * QKV_LD + s * 8;
        cp_async16(ks_b + (uint32_t)(r * FP2 + s * 8) * 2, Kg + go);
        cp_async16(vs_b + (uint32_t)(r * FP2 + s * 8) * 2, Vg + go);
    }
    CP_COMMIT();
    CP_WAIT(0);            // Q and KV0 both resident (own groups)
    __syncthreads();       // all threads' copies visible

    // Q fragments, cached for whole kernel
    uint32_t qf[4][4];
    #pragma unroll
    for (int ks = 0; ks < 4; ks++) {
        uint32_t addr = qs_b +
            (uint32_t)((wid * 16 + (lane & 15)) * FP2 + ks * 16 + (lane >> 4) * 8) * 2;
        ldsm_x4(qf[ks][0], qf[ks][1], qf[ks][2], qf[ks][3], addr);
    }

    float o[8][4];
    #pragma unroll
    for (int j = 0; j < 8; j++)
        #pragma unroll
        for (int r = 0; r < 4; r++) o[j][r] = 0.f;
    float m0 = -1e30f, m1 = -1e30f, l0 = 0.f, l1 = 0.f;
    const float scale = 0.125f;

    for (int kt = 0; kt <= qi; ++kt) {
        const int st = kt & 1;
        if (kt > 0) {
            CP_WAIT(0);        // own copies of KV_kt done
            __syncthreads();   // all threads' KV_kt visible; stage st^1 free
        }
        // issue next tile's loads BEFORE compute (DMA overlaps MMA)
        if (kt < qi) {
            const uint32_t so = (uint32_t)(st ^ 1) * kv_stage;
            #pragma unroll
            for (int i = 0; i < 4; i++) {
                int idx = tid + i * 128;
                int r = idx >> 3, s = idx & 7;
                size_t go = (size_t)((kt + 1) * 64 + r) * QKV_LD + s * 8;
                cp_async16(ks_b + so + (uint32_t)(r * FP2 + s * 8) * 2, Kg + go);
                cp_async16(vs_b + so + (uint32_t)(r * FP2 + s * 8) * 2, Vg + go);
            }
            CP_COMMIT();
        }

        // ---- S = Q K^T ----
        float sf[8][4];
        #pragma unroll
        for (int j = 0; j < 8; j++)
            #pragma unroll
            for (int r = 0; r < 4; r++) sf[j][r] = 0.f;

        const uint32_t ks_st = ks_b + (uint32_t)st * kv_stage;
        #pragma unroll
        for (int ks = 0; ks < 4; ks++) {
            #pragma unroll
            for (int nb = 0; nb < 4; nb++) {
                uint32_t r0, r1, r2, r3;
                uint32_t addr = ks_st +
                    (uint32_t)((nb * 16 + (lane & 15)) * FP2 + ks * 16 + (lane >> 4) * 8) * 2;
                ldsm_x4(r0, r1, r2, r3, addr);
                mma16816(sf[nb * 2 + 0], qf[ks], r0, r2);
                mma16816(sf[nb * 2 + 1], qf[ks], r1, r3);
            }
        }

        // ---- scale + causal mask (diagonal tile only) ----
        if (kt == qi) {
            const int rg0 = wid * 16 + (lane >> 2);
            #pragma unroll
            for (int j = 0; j < 8; j++) {
                const int c0 = j * 8 + (lane & 3) * 2;
                sf[j][0] = (c0     > rg0    ) ? -1e30f : sf[j][0] * scale;
                sf[j][1] = (c0 + 1 > rg0    ) ? -1e30f : sf[j][1] * scale;
                sf[j][2] = (c0     > rg0 + 8) ? -1e30f : sf[j][2] * scale;
                sf[j][3] = (c0 + 1 > rg0 + 8) ? -1e30f : sf[j][3] * scale;
            }
        } else {
            #pragma unroll
            for (int j = 0; j < 8; j++) {
                sf[j][0] *= scale; sf[j][1] *= scale;
                sf[j][2] *= scale; sf[j][3] *= scale;
            }
        }

        // ---- online softmax ----
        float t0 = -1e30f, t1 = -1e30f;
        #pragma unroll
        for (int j = 0; j < 8; j++) {
            t0 = fmaxf(t0, fmaxf(sf[j][0], sf[j][1]));
            t1 = fmaxf(t1, fmaxf(sf[j][2], sf[j][3]));
        }
        t0 = fmaxf(t0, __shfl_xor_sync(0xffffffffu, t0, 1));
        t0 = fmaxf(t0, __shfl_xor_sync(0xffffffffu, t0, 2));
        t1 = fmaxf(t1, __shfl_xor_sync(0xffffffffu, t1, 1));
        t1 = fmaxf(t1, __shfl_xor_sync(0xffffffffu, t1, 2));

        const float mn0 = fmaxf(m0, t0), mn1 = fmaxf(m1, t1);
        const float a0 = __expf(m0 - mn0), a1 = __expf(m1 - mn1);
        float ps0 = 0.f, ps1 = 0.f;
        #pragma unroll
        for (int j = 0; j < 8; j++) {
            sf[j][0] = __expf(sf[j][0] - mn0);
            sf[j][1] = __expf(sf[j][1] - mn0);
            sf[j][2] = __expf(sf[j][2] - mn1);
            sf[j][3] = __expf(sf[j][3] - mn1);
            ps0 += sf[j][0] + sf[j][1];
            ps1 += sf[j][2] + sf[j][3];
        }
        ps0 += __shfl_xor_sync(0xffffffffu, ps0, 1);
        ps0 += __shfl_xor_sync(0xffffffffu, ps0, 2);
        ps1 += __shfl_xor_sync(0xffffffffu, ps1, 1);
        ps1 += __shfl_xor_sync(0xffffffffu, ps1, 2);
        l0 = l0 * a0 + ps0; l1 = l1 * a1 + ps1;
        m0 = mn0; m1 = mn1;
        #pragma unroll
        for (int j = 0; j < 8; j++) {
            o[j][0] *= a0; o[j][1] *= a0;
            o[j][2] *= a1; o[j][3] *= a1;
        }

        // ---- P -> fp16 A-fragments ----
        uint32_t pf[4][4];
        #pragma unroll
        for (int kk = 0; kk < 4; kk++) {
            pf[kk][0] = packh2(sf[2*kk][0],   sf[2*kk][1]);
            pf[kk][1] = packh2(sf[2*kk][2],   sf[2*kk][3]);
            pf[kk][2] = packh2(sf[2*kk+1][0], sf[2*kk+1][1]);
            pf[kk][3] = packh2(sf[2*kk+1][2], sf[2*kk+1][3]);
        }

        // ---- O += P V ----
        const uint32_t vs_st = vs_b + (uint32_t)st * kv_stage;
        #pragma unroll
        for (int kk = 0; kk < 4; kk++) {
            #pragma unroll
            for (int ns = 0; ns < 4; ns++) {
                uint32_t v0, v1, v2, v3;
                uint32_t addr = vs_st +
                    (uint32_t)((kk * 16 + (lane & 7) + 8 * ((lane >> 3) & 1)) * FP2 +
                               ns * 16 + 8 * (lane >> 4)) * 2;
                ldsm_x4_t(v0, v1, v2, v3, addr);
                mma16816(o[2 * ns + 0], pf[kk], v0, v1);
                mma16816(o[2 * ns + 1], pf[kk], v2, v3);
            }
        }
    }

    // ---- epilogue ----
    const float i0 = 1.f / l0, i1 = 1.f / l1;
    const size_t gr0 = qrow0 + wid * 16 + (lane >> 2);
    #pragma unroll
    for (int j = 0; j < 8; j++) {
        const int col = h * DK + j * 8 + (lane & 3) * 2;
        *(__half2*)(O + gr0 * D_MODEL + col) =
            __floats2half2_rn(o[j][0] * i0, o[j][1] * i0);
        *(__half2*)(O + (gr0 + 8) * D_MODEL + col) =
            __floats2half2_rn(o[j][2] * i1, o[j][3] * i1);
    }
}

// ================= host =================
extern "C" void kernel_launch(void* const* d_in, const int* in_sizes, int n_in,
                              void* d_out, int out_size)
{
    const float* x  = (const float*)d_in[0];
    const float* wq = (const float*)d_in[1];
    const float* wk = (const float*)d_in[2];
    const float* wv = (const float*)d_in[3];
    const float* wo = (const float*)d_in[4];
    const float* w1 = (const float*)d_in[5];
    const float* w2 = (const float*)d_in[6];
    const float* g1 = (const float*)d_in[7];
    const float* g2 = (const float*)d_in[8];
    float* out = (float*)d_out;

    __half *xnh, *qkvh, *atth, *ffhh, *w3h, *woh, *w1h, *w2h;
    float *x1;
    cudaGetSymbolAddress((void**)&xnh,  g_xnh);
    cudaGetSymbolAddress((void**)&qkvh, g_qkvh);
    cudaGetSymbolAddress((void**)&atth, g_atth);
    cudaGetSymbolAddress((void**)&x1,   g_x1);
    cudaGetSymbolAddress((void**)&ffhh, g_ffhh);
    cudaGetSymbolAddress((void**)&w3h,  g_w3h);
    cudaGetSymbolAddress((void**)&woh,  g_woh);
    cudaGetSymbolAddress((void**)&w1h,  g_w1h);
    cudaGetSymbolAddress((void**)&w2h,  g_w2h);

    cudaFuncSetAttribute(hgemm_mma<1>, cudaFuncAttributeMaxDynamicSharedMemorySize, HG_SMEM);
    cudaFuncSetAttribute(hgemm_mma<2>, cudaFuncAttributeMaxDynamicSharedMemorySize, HG_SMEM);
    cudaFuncSetAttribute(hgemm_mma<3>, cudaFuncAttributeMaxDynamicSharedMemorySize, HG_SMEM);

    // 0+1. fused: rmsnorm1 (4096 blocks) + all weight f2h (12288 blocks)
    pre_kernel<<<MTOT + (12 * D_MODEL * D_MODEL) / 1024, 256>>>(
        x, g1, xnh, wq, wk, wv, wo, w1, w2, w3h, woh, w1h, w2h);

    // 2. qkv = xn @ [wq|wk|wv]^T   (fused, fp16 out)
    dim3 gqkv(QKV_LD / 128, MTOT / 128);
    hgemm_mma<3><<<gqkv, 256, HG_SMEM>>>(xnh, w3h, nullptr, nullptr, qkvh, MTOT, QKV_LD, D_MODEL);

    // 3. att = causal_attention(q,k,v)
    flash_mma<<<dim3(SEQ / 64, BATCH * NHEAD), 128>>>(qkvh, atth);

    // 4. x1 = x + att @ wo^T
    dim3 gproj(D_MODEL / 128, MTOT / 128);
    hgemm_mma<1><<<gproj, 256, HG_SMEM>>>(atth, woh, x, x1, nullptr, MTOT, D_MODEL, D_MODEL);

    // 5. xn = rmsnorm(x1, g2)
    rmsnorm_h_kernel<<<MTOT, 256>>>(x1, g2, xnh);

    // 6. ffh = gelu(xn @ w1^T)
    dim3 gff1(DFF / 128, MTOT / 128);
    hgemm_mma<2><<<gff1, 256, HG_SMEM>>>(xnh, w1h, nullptr, nullptr, ffhh, MTOT, DFF, D_MODEL);

    // 7. out = x1 + ffh @ w2^T
    hgemm_mma<1><<<gproj, 256, HG_SMEM>>>(ffhh, w2h, x1, out, nullptr, MTOT, D_MODEL, DFF);
}